// round 13
// baseline (speedup 1.0000x reference)
#include <cuda_runtime.h>
#include <cuda_bf16.h>
#include <cstdint>

#define DIM   1024
#define BATCH 4
#define SEQ   1024
#define NHEAD 16
#define HD    64
#define NROWS (BATCH*SEQ)     /* 4096 */
#define BH    (BATCH*NHEAD)   /* 64   */
#define TOPK  32

#define F_INF   __int_as_float(0x7f800000)
#define F_NINF  __int_as_float(0xff800000)

// ---------------- scratch (device globals; no allocation allowed) ----------
__device__ float g_xn[(size_t)NROWS*DIM];          // 16 MB  normalized x
__device__ float g_q[(size_t)BH*SEQ*HD];           // 16 MB  [b,h,n,d] (pre-scaled)
__device__ float g_k[(size_t)BH*SEQ*HD];           // 16 MB
__device__ float g_v[(size_t)BH*SEQ*HD];           // 16 MB
__device__ float g_sim[(size_t)BH*SEQ*SEQ];        // 256 MB [b,h,i,j]
__device__ float g_xsum[(size_t)NROWS*DIM];        // 16 MB  [b,n,(h d)] RAW sums
__device__ unsigned g_mm[2];                       // encoded min / max

// ---------------- helpers --------------------------------------------------
__device__ __forceinline__ uint32_t smem_u32(const void* p) {
    uint32_t a;
    asm("{ .reg .u64 t; cvta.to.shared.u64 t, %1; cvt.u32.u64 %0, t; }"
        : "=r"(a) : "l"(p));
    return a;
}

// fp32 float4 -> packed bf16 hi (uint2) and lo residual (uint2)
__device__ __forceinline__ void f4_hilo(float4 v, uint2& hi, uint2& lo) {
    __nv_bfloat16 h0 = __float2bfloat16(v.x), h1 = __float2bfloat16(v.y);
    __nv_bfloat16 h2 = __float2bfloat16(v.z), h3 = __float2bfloat16(v.w);
    __nv_bfloat16 l0 = __float2bfloat16(v.x - __bfloat162float(h0));
    __nv_bfloat16 l1 = __float2bfloat16(v.y - __bfloat162float(h1));
    __nv_bfloat16 l2 = __float2bfloat16(v.z - __bfloat162float(h2));
    __nv_bfloat16 l3 = __float2bfloat16(v.w - __bfloat162float(h3));
    hi.x = (uint32_t)__bfloat16_as_ushort(h0) | ((uint32_t)__bfloat16_as_ushort(h1) << 16);
    hi.y = (uint32_t)__bfloat16_as_ushort(h2) | ((uint32_t)__bfloat16_as_ushort(h3) << 16);
    lo.x = (uint32_t)__bfloat16_as_ushort(l0) | ((uint32_t)__bfloat16_as_ushort(l1) << 16);
    lo.y = (uint32_t)__bfloat16_as_ushort(l2) | ((uint32_t)__bfloat16_as_ushort(l3) << 16);
}

__device__ __forceinline__ unsigned fenc(float f) {
    unsigned u = __float_as_uint(f);
    return (u & 0x80000000u) ? ~u : (u | 0x80000000u);
}
__device__ __forceinline__ float fdec(unsigned u) {
    return __uint_as_float((u & 0x80000000u) ? (u ^ 0x80000000u) : ~u);
}

#define LDSM_X4(r, a) \
    asm volatile("ldmatrix.sync.aligned.m8n8.x4.shared.b16 {%0,%1,%2,%3}, [%4];" \
        : "=r"((r)[0]), "=r"((r)[1]), "=r"((r)[2]), "=r"((r)[3]) : "r"(a))
#define LDSM_X2(r, a) \
    asm volatile("ldmatrix.sync.aligned.m8n8.x2.shared.b16 {%0,%1}, [%2];" \
        : "=r"((r)[0]), "=r"((r)[1]) : "r"(a))
#define MMA16816(d, a, b) \
    asm volatile("mma.sync.aligned.m16n8k16.row.col.f32.bf16.bf16.f32 " \
        "{%0,%1,%2,%3}, {%4,%5,%6,%7}, {%8,%9}, {%0,%1,%2,%3};" \
        : "+f"((d)[0]), "+f"((d)[1]), "+f"((d)[2]), "+f"((d)[3]) \
        : "r"((a)[0]), "r"((a)[1]), "r"((a)[2]), "r"((a)[3]), "r"((b)[0]), "r"((b)[1]))

__global__ void init_mm_kernel() {
    g_mm[0] = 0xFFFFFFFFu;
    g_mm[1] = 0u;
}

// ---------------- LayerNorm: one block per row, fp32 out -------------------
__global__ void layernorm_kernel(const float* __restrict__ x,
                                 const float* __restrict__ gamma,
                                 const float* __restrict__ beta) {
    int row = blockIdx.x, tid = threadIdx.x;
    const float4* xr = reinterpret_cast<const float4*>(x + (size_t)row * DIM);
    float4 xv = xr[tid];
    float s  = xv.x + xv.y + xv.z + xv.w;
    float ss = fmaf(xv.x, xv.x, fmaf(xv.y, xv.y, fmaf(xv.z, xv.z, xv.w * xv.w)));
    #pragma unroll
    for (int o = 16; o; o >>= 1) {
        s  += __shfl_xor_sync(0xffffffffu, s,  o);
        ss += __shfl_xor_sync(0xffffffffu, ss, o);
    }
    __shared__ float rs[8], rss[8];
    __shared__ float sm_mean, sm_inv;
    int w = tid >> 5, l = tid & 31;
    if (!l) { rs[w] = s; rss[w] = ss; }
    __syncthreads();
    if (tid == 0) {
        float S = 0.f, SS = 0.f;
        #pragma unroll
        for (int i = 0; i < 8; i++) { S += rs[i]; SS += rss[i]; }
        float mean = S * (1.f / DIM);
        float var  = SS * (1.f / DIM) - mean * mean;
        sm_mean = mean;
        sm_inv  = rsqrtf(var + 1e-5f);
    }
    __syncthreads();
    float mean = sm_mean, inv = sm_inv;
    float4 gv = reinterpret_cast<const float4*>(gamma)[tid];
    float4 bv = reinterpret_cast<const float4*>(beta)[tid];
    float4 o;
    o.x = (xv.x - mean) * inv * gv.x + bv.x;
    o.y = (xv.y - mean) * inv * gv.y + bv.y;
    o.z = (xv.z - mean) * inv * gv.z + bv.z;
    o.w = (xv.w - mean) * inv * gv.w + bv.w;
    reinterpret_cast<float4*>(g_xn)[(size_t)row * (DIM / 4) + tid] = o;
}

// ============ BIG GEMM (K=1024): single-buffer, K-chunk 64 =================
// R7-proven structure (store; sync; prefetch; MMA; sync) with chunk doubled:
// 16 chunks instead of 32 -> half the barriers. 128x128 CTA tile, 8 warps
// (2x4), warp tile 64x32, single 72KB smem stage, 1 CTA/SM (no reg cap).
// EPI 1: qkv   A=g_xn,   B=w_qkv -> scatter q(scaled)/k/v (fp32)
// EPI 2: out   A=exp((g_xsum-mn)*inv) on the fly, B=w_out -> C + bias
#define R2STRIDE 144
#define P2SIZE   (128*R2STRIDE)    /* 18432 */
#define BIGSMEM  (4*P2SIZE)        /* 73728 */

template<int EPI>
__global__ __launch_bounds__(256)
void mma_gemm_big(const float* __restrict__ Bw, float* __restrict__ C,
                  const float* __restrict__ bias) {
    extern __shared__ __align__(16) char dynsm[];

    const float* A = (EPI == 1) ? g_xn : g_xsum;
    const float* B = Bw;

    float emn = 0.f, einv = 0.f;
    if (EPI == 2) {
        emn = fdec(g_mm[0]);
        float emx = fdec(g_mm[1]);
        einv = 1.0f / (emx - emn);
    }

    int tid = threadIdx.x;
    int bm = blockIdx.y * 128, bn = blockIdx.x * 128;

    // loader: 2 threads/row, 32 fp32 each per chunk (chunk = 64 cols)
    int lrow = tid >> 1, lcb = (tid & 1) * 32;
    const float* Ap = A + (size_t)(bm + lrow) * DIM + lcb;
    const float* Bp = B + (size_t)(bn + lrow) * DIM + lcb;

    float4 ar[8], br[8];
    #pragma unroll
    for (int i = 0; i < 8; i++) {
        ar[i] = *(const float4*)(Ap + i * 4);
        br[i] = *(const float4*)(Bp + i * 4);
    }

    int w = tid >> 5, l = tid & 31;
    int wm = w >> 2, wn = w & 3;
    uint32_t sb = smem_u32(dynsm);
    uint32_t aLane = (uint32_t)((l & 15) * R2STRIDE + (l >> 4) * 16);
    uint32_t bLane = (uint32_t)((l & 7) * R2STRIDE + ((l >> 3) & 1) * 16);
    uint32_t aWarp = (uint32_t)(wm * 64 * R2STRIDE);
    uint32_t bWarp = (uint32_t)(wn * 32 * R2STRIDE);

    float acc[4][4][4] = {};

    const int NS = DIM / 64;   // 16 chunks
    #pragma unroll 1
    for (int s = 0; s < NS; s++) {
        if (s) __syncthreads();            // readers of previous chunk done
        #pragma unroll
        for (int i = 0; i < 8; i++) {
            uint32_t off = (uint32_t)(lrow * R2STRIDE + (lcb + i * 4) * 2);
            float4 av = ar[i];
            if (EPI == 2) {                // fused exp((x-mn)*inv)
                av.x = expf((av.x - emn) * einv);
                av.y = expf((av.y - emn) * einv);
                av.z = expf((av.z - emn) * einv);
                av.w = expf((av.w - emn) * einv);
            }
            uint2 h, lo;
            f4_hilo(av, h, lo);
            *(uint2*)(dynsm + off) = h;
            *(uint2*)(dynsm + P2SIZE + off) = lo;
            f4_hilo(br[i], h, lo);
            *(uint2*)(dynsm + 2 * P2SIZE + off) = h;
            *(uint2*)(dynsm + 3 * P2SIZE + off) = lo;
        }
        __syncthreads();
        if (s + 1 < NS) {                  // prefetch next chunk during HMMA
            #pragma unroll
            for (int i = 0; i < 8; i++) {
                ar[i] = *(const float4*)(Ap + (s + 1) * 64 + i * 4);
                br[i] = *(const float4*)(Bp + (s + 1) * 64 + i * 4);
            }
        }
        uint32_t aAhi = sb, aAlo = sb + P2SIZE;
        uint32_t aBhi = sb + 2 * P2SIZE, aBlo = sb + 3 * P2SIZE;
        #pragma unroll
        for (int kk = 0; kk < 64; kk += 16) {
            uint32_t af[4][2][4];
            #pragma unroll
            for (int mi = 0; mi < 4; mi++) {
                uint32_t o = aWarp + (uint32_t)(mi * 16 * R2STRIDE + kk * 2) + aLane;
                LDSM_X4(af[mi][0], aAhi + o);
                LDSM_X4(af[mi][1], aAlo + o);
            }
            uint32_t bf[4][2][2];
            #pragma unroll
            for (int nj = 0; nj < 4; nj++) {
                uint32_t o = bWarp + (uint32_t)(nj * 8 * R2STRIDE + kk * 2) + bLane;
                LDSM_X2(bf[nj][0], aBhi + o);
                LDSM_X2(bf[nj][1], aBlo + o);
            }
            #pragma unroll
            for (int mi = 0; mi < 4; mi++)
                #pragma unroll
                for (int nj = 0; nj < 4; nj++) {
                    MMA16816(acc[mi][nj], af[mi][0], bf[nj][0]);   // hi*hi
                    MMA16816(acc[mi][nj], af[mi][0], bf[nj][1]);   // hi*lo
                    MMA16816(acc[mi][nj], af[mi][1], bf[nj][0]);   // lo*hi
                }
        }
    }

    // ---------------- epilogue from register accumulators ----------------
    #pragma unroll
    for (int mi = 0; mi < 4; mi++) {
        int row0 = bm + wm * 64 + mi * 16 + (l >> 2);
        #pragma unroll
        for (int nj = 0; nj < 4; nj++) {
            int col = bn + wn * 32 + nj * 8 + (l & 3) * 2;
            #pragma unroll
            for (int half = 0; half < 2; half++) {
                int m = row0 + half * 8;
                float v0 = acc[mi][nj][half * 2 + 0];
                float v1 = acc[mi][nj][half * 2 + 1];
                if (EPI == 1) {
                    int which = col >> 10;          // 0=q 1=k 2=v
                    int hh = (col & 1023) >> 6;
                    int dd = col & 63;
                    int bb = m >> 10, nn = m & 1023;
                    size_t o = (((size_t)(bb * NHEAD + hh)) * SEQ + nn) * HD + dd;
                    float sc = (which == 0) ? 0.125f : 1.0f;   // q pre-scale d^-0.5
                    float* dst = (which == 0 ? g_q : which == 1 ? g_k : g_v) + o;
                    *(float2*)dst = make_float2(v0 * sc, v1 * sc);
                } else {
                    float2* dst = (float2*)(C + (size_t)m * DIM + col);
                    *dst = make_float2(v0 + bias[col], v1 + bias[col + 1]);
                }
            }
        }
    }
}

// ============ SIM GEMM (K=64): R11 db mainloop + staged epilogue ===========
// 128x128 CTA tile, K-chunk 32, double-buffered 2x40KB, one sync/chunk.
// Epilogue staged through smem -> coalesced float4 row writes to g_sim.
#define RSTRIDE 80
#define GSTAGE  40960
#define GSMEM   (2*GSTAGE)   /* 81920; also covers 128x132 fp32 staging */

__global__ __launch_bounds__(256, 2)
void mma_gemm_sim(int dummy) {
    extern __shared__ __align__(16) char dynsm[];

    size_t off0 = (size_t)blockIdx.z * SEQ * HD;
    const float* A = g_q + off0;
    const float* B = g_k + off0;

    int tid = threadIdx.x;
    int bm = blockIdx.y * 128, bn = blockIdx.x * 128;

    int lrow = tid >> 1, lcb = (tid & 1) * 16;
    const float* Ap = A + (size_t)(bm + lrow) * HD + lcb;
    const float* Bp = B + (size_t)(bn + lrow) * HD + lcb;

    float4 ar[4], br[4];
    #pragma unroll
    for (int i = 0; i < 4; i++) {
        ar[i] = *(const float4*)(Ap + i * 4);
        br[i] = *(const float4*)(Bp + i * 4);
    }
    {   // chunk 0 -> stage 0
        char* st = dynsm;
        #pragma unroll
        for (int i = 0; i < 4; i++) {
            uint32_t off = (uint32_t)(lrow * RSTRIDE + (lcb + i * 4) * 2);
            uint2 h, lo;
            f4_hilo(ar[i], h, lo);
            *(uint2*)(st + off) = h;            *(uint2*)(st + 10240 + off) = lo;
            f4_hilo(br[i], h, lo);
            *(uint2*)(st + 20480 + off) = h;    *(uint2*)(st + 30720 + off) = lo;
        }
    }

    int w = tid >> 5, l = tid & 31;
    int wm = w >> 2, wn = w & 3;
    uint32_t sb = smem_u32(dynsm);
    uint32_t aLane = (uint32_t)((l & 15) * RSTRIDE + (l >> 4) * 16);
    uint32_t bLane = (uint32_t)((l & 7) * RSTRIDE + ((l >> 3) & 1) * 16);
    uint32_t aWarp = (uint32_t)(wm * 64 * RSTRIDE);
    uint32_t bWarp = (uint32_t)(wn * 32 * RSTRIDE);

    float acc[4][4][4] = {};

    const int NS = HD / 32;   // 2 chunks
    #pragma unroll 1
    for (int s = 0; s < NS; s++) {
        __syncthreads();
        if (s + 1 < NS) {
            #pragma unroll
            for (int i = 0; i < 4; i++) {
                ar[i] = *(const float4*)(Ap + (s + 1) * 32 + i * 4);
                br[i] = *(const float4*)(Bp + (s + 1) * 32 + i * 4);
            }
        }
        uint32_t cur = sb + (uint32_t)(s & 1) * GSTAGE;
        uint32_t aAhi = cur, aAlo = cur + 10240, aBhi = cur + 20480, aBlo = cur + 30720;
        #pragma unroll
        for (int kk = 0; kk < 32; kk += 16) {
            uint32_t af[4][2][4];
            #pragma unroll
            for (int mi = 0; mi < 4; mi++) {
                uint32_t o = aWarp + (uint32_t)(mi * 16 * RSTRIDE + kk * 2) + aLane;
                LDSM_X4(af[mi][0], aAhi + o);
                LDSM_X4(af[mi][1], aAlo + o);
            }
            uint32_t bf[4][2][2];
            #pragma unroll
            for (int nj = 0; nj < 4; nj++) {
                uint32_t o = bWarp + (uint32_t)(nj * 8 * RSTRIDE + kk * 2) + bLane;
                LDSM_X2(bf[nj][0], aBhi + o);
                LDSM_X2(bf[nj][1], aBlo + o);
            }
            #pragma unroll
            for (int mi = 0; mi < 4; mi++)
                #pragma unroll
                for (int nj = 0; nj < 4; nj++) {
                    MMA16816(acc[mi][nj], af[mi][0], bf[nj][0]);
                    MMA16816(acc[mi][nj], af[mi][0], bf[nj][1]);
                    MMA16816(acc[mi][nj], af[mi][1], bf[nj][0]);
                }
        }
        if (s + 1 < NS) {
            char* st = dynsm + ((s + 1) & 1) * GSTAGE;
            #pragma unroll
            for (int i = 0; i < 4; i++) {
                uint32_t off = (uint32_t)(lrow * RSTRIDE + (lcb + i * 4) * 2);
                uint2 h, lo;
                f4_hilo(ar[i], h, lo);
                *(uint2*)(st + off) = h;            *(uint2*)(st + 10240 + off) = lo;
                f4_hilo(br[i], h, lo);
                *(uint2*)(st + 20480 + off) = h;    *(uint2*)(st + 30720 + off) = lo;
            }
        }
    }

    // ---- staged epilogue: acc -> smem (128x132 fp32) -> coalesced STG ----
    __syncthreads();                       // all warps done with smem stages
    float* ssc = (float*)dynsm;            // 128*132*4 = 67584 <= 81920
    #pragma unroll
    for (int mi = 0; mi < 4; mi++) {
        int rloc0 = wm * 64 + mi * 16 + (l >> 2);
        #pragma unroll
        for (int nj = 0; nj < 4; nj++) {
            int cloc = wn * 32 + nj * 8 + (l & 3) * 2;
            #pragma unroll
            for (int half = 0; half < 2; half++) {
                int rloc = rloc0 + half * 8;
                *(float2*)(ssc + rloc * 132 + cloc) =
                    make_float2(acc[mi][nj][half * 2 + 0], acc[mi][nj][half * 2 + 1]);
            }
        }
    }
    __syncthreads();
    {
        int r = tid >> 1, ch = (tid & 1) * 64;
        const float4* src = (const float4*)(ssc + r * 132 + ch);
        float4* dst = (float4*)(g_sim + (size_t)blockIdx.z * SEQ * SEQ
                                + (size_t)(bm + r) * SEQ + bn + ch);
        #pragma unroll
        for (int j = 0; j < 16; j++) dst[j] = src[j];
    }
}

// ------- top-32 select + gather-sum + fused global min/max -----------------
__global__ void topk_gather_kernel() {
    int warp = threadIdx.x >> 5;
    int lane = threadIdx.x & 31;
    int row  = blockIdx.x * 4 + warp;          // ((b*16+h)*1024 + nq)
    int bh   = row >> 10;

    const float* srow = g_sim + (size_t)row * SEQ;
    float vals[32];
    #pragma unroll
    for (int i = 0; i < 32; i++) vals[i] = srow[i * 32 + lane];   // j = i*32+lane

    float best = vals[0]; int bi = 0;
    #pragma unroll
    for (int i = 1; i < 32; i++)
        if (vals[i] > best) { best = vals[i]; bi = i; }

    int myidx = 0;
    #pragma unroll 1
    for (int r = 0; r < TOPK; r++) {
        unsigned e = fenc(best);
        unsigned wmax = __reduce_max_sync(0xffffffffu, e);
        unsigned msk = __ballot_sync(0xffffffffu, e == wmax);
        int wl = __ffs(msk) - 1;
        int wbi = __shfl_sync(0xffffffffu, bi, wl);
        int widx = wbi * 32 + wl;              // winning key index
        if (lane == r) myidx = widx;
        if (lane == wl) {                       // winner rescans its registers
            float nb = F_NINF; int nbi = 0;
            #pragma unroll
            for (int i = 0; i < 32; i++) {
                if (i == bi) vals[i] = F_NINF;
                if (vals[i] > nb) { nb = vals[i]; nbi = i; }
            }
            best = nb; bi = nbi;
        }
    }

    // unweighted gather-sum of the 32 selected V rows
    const float* vbase = g_v + (size_t)bh * SEQ * HD;
    float a0 = 0.f, a1 = 0.f;
    #pragma unroll 1
    for (int r = 0; r < TOPK; r++) {
        int idx = __shfl_sync(0xffffffffu, myidx, r);
        const float* vr = vbase + (size_t)idx * HD;
        a0 += vr[lane];
        a1 += vr[lane + 32];
    }

    int bb = row >> 14;
    int hh = (row >> 10) & 15;
    int nq = row & 1023;
    size_t o = ((size_t)(bb * SEQ + nq)) * DIM + hh * HD;   // [b,n,(h d)]
    g_xsum[o + lane]      = a0;
    g_xsum[o + lane + 32] = a1;

    // ---- fused global min/max: every g_xsum value is in exactly one warp --
    float mn = fminf(a0, a1), mx = fmaxf(a0, a1);
    #pragma unroll
    for (int off = 16; off; off >>= 1) {
        mn = fminf(mn, __shfl_xor_sync(0xffffffffu, mn, off));
        mx = fmaxf(mx, __shfl_xor_sync(0xffffffffu, mx, off));
    }
    __shared__ float smn[4], smx[4];
    if (!lane) { smn[warp] = mn; smx[warp] = mx; }
    __syncthreads();
    if (threadIdx.x == 0) {
        #pragma unroll
        for (int i = 1; i < 4; i++) { mn = fminf(mn, smn[i]); mx = fmaxf(mx, smx[i]); }
        atomicMin(&g_mm[0], fenc(mn));
        atomicMax(&g_mm[1], fenc(mx));
    }
}

// ---------------- launch ---------------------------------------------------
extern "C" void kernel_launch(void* const* d_in, const int* in_sizes, int n_in,
                              void* d_out, int out_size) {
    const float* x      = (const float*)d_in[0];
    const float* gamma  = (const float*)d_in[1];
    const float* beta   = (const float*)d_in[2];
    const float* w_qkv  = (const float*)d_in[3];
    const float* w_out  = (const float*)d_in[4];
    const float* b_out  = (const float*)d_in[5];
    float* out = (float*)d_out;

    cudaFuncSetAttribute((const void*)mma_gemm_big<1>,
                         cudaFuncAttributeMaxDynamicSharedMemorySize, BIGSMEM);
    cudaFuncSetAttribute((const void*)mma_gemm_big<2>,
                         cudaFuncAttributeMaxDynamicSharedMemorySize, BIGSMEM);
    cudaFuncSetAttribute((const void*)mma_gemm_sim,
                         cudaFuncAttributeMaxDynamicSharedMemorySize, GSMEM);

    init_mm_kernel<<<1, 1>>>();
    layernorm_kernel<<<NROWS, 256>>>(x, gamma, beta);
    // qkv: [4096,1024] @ [3072,1024]^T (HMMA bf16x3, K-chunk 64)
    mma_gemm_big<1><<<dim3(24, 32, 1), 256, BIGSMEM>>>(w_qkv, nullptr, nullptr);
    // sim: 64 batched [1024,64] @ [1024,64]^T (db + staged epilogue)
    mma_gemm_sim<<<dim3(8, 8, BH), 256, GSMEM>>>(0);
    // top-32 select + gather-sum + fused min/max
    topk_gather_kernel<<<BH * SEQ / 4, 128>>>();
    // out: exp-normalize fused into A-loader; [4096,1024] @ [1024,1024]^T + bias
    mma_gemm_big<2><<<dim3(8, 32, 1), 256, BIGSMEM>>>(w_out, out, b_out);
}

// round 14
// speedup vs baseline: 2.0159x; 2.0159x over previous
#include <cuda_runtime.h>
#include <cuda_bf16.h>
#include <cstdint>

#define DIM   1024
#define BATCH 4
#define SEQ   1024
#define NHEAD 16
#define HD    64
#define NROWS (BATCH*SEQ)     /* 4096 */
#define BH    (BATCH*NHEAD)   /* 64   */
#define TOPK  32

#define F_INF   __int_as_float(0x7f800000)
#define F_NINF  __int_as_float(0xff800000)

// ---------------- scratch (device globals; no allocation allowed) ----------
__device__ float g_xn[(size_t)NROWS*DIM];          // 16 MB  normalized x
__device__ float g_q[(size_t)BH*SEQ*HD];           // 16 MB  [b,h,n,d] (pre-scaled)
__device__ float g_k[(size_t)BH*SEQ*HD];           // 16 MB
__device__ float g_v[(size_t)BH*SEQ*HD];           // 16 MB
__device__ float g_sim[(size_t)BH*SEQ*SEQ];        // 256 MB [b,h,i,j]
__device__ float g_xsum[(size_t)NROWS*DIM];        // 16 MB  [b,n,(h d)] RAW sums
__device__ unsigned g_mm[2];                       // encoded min / max

// ---------------- helpers --------------------------------------------------
__device__ __forceinline__ uint32_t smem_u32(const void* p) {
    uint32_t a;
    asm("{ .reg .u64 t; cvta.to.shared.u64 t, %1; cvt.u32.u64 %0, t; }"
        : "=r"(a) : "l"(p));
    return a;
}

// fp32 float4 -> packed bf16 hi (uint2) and lo residual (uint2)
__device__ __forceinline__ void f4_hilo(float4 v, uint2& hi, uint2& lo) {
    __nv_bfloat16 h0 = __float2bfloat16(v.x), h1 = __float2bfloat16(v.y);
    __nv_bfloat16 h2 = __float2bfloat16(v.z), h3 = __float2bfloat16(v.w);
    __nv_bfloat16 l0 = __float2bfloat16(v.x - __bfloat162float(h0));
    __nv_bfloat16 l1 = __float2bfloat16(v.y - __bfloat162float(h1));
    __nv_bfloat16 l2 = __float2bfloat16(v.z - __bfloat162float(h2));
    __nv_bfloat16 l3 = __float2bfloat16(v.w - __bfloat162float(h3));
    hi.x = (uint32_t)__bfloat16_as_ushort(h0) | ((uint32_t)__bfloat16_as_ushort(h1) << 16);
    hi.y = (uint32_t)__bfloat16_as_ushort(h2) | ((uint32_t)__bfloat16_as_ushort(h3) << 16);
    lo.x = (uint32_t)__bfloat16_as_ushort(l0) | ((uint32_t)__bfloat16_as_ushort(l1) << 16);
    lo.y = (uint32_t)__bfloat16_as_ushort(l2) | ((uint32_t)__bfloat16_as_ushort(l3) << 16);
}

__device__ __forceinline__ unsigned fenc(float f) {
    unsigned u = __float_as_uint(f);
    return (u & 0x80000000u) ? ~u : (u | 0x80000000u);
}
__device__ __forceinline__ float fdec(unsigned u) {
    return __uint_as_float((u & 0x80000000u) ? (u ^ 0x80000000u) : ~u);
}

#define LDSM_X4(r, a) \
    asm volatile("ldmatrix.sync.aligned.m8n8.x4.shared.b16 {%0,%1,%2,%3}, [%4];" \
        : "=r"((r)[0]), "=r"((r)[1]), "=r"((r)[2]), "=r"((r)[3]) : "r"(a))
#define LDSM_X2(r, a) \
    asm volatile("ldmatrix.sync.aligned.m8n8.x2.shared.b16 {%0,%1}, [%2];" \
        : "=r"((r)[0]), "=r"((r)[1]) : "r"(a))
#define MMA16816(d, a, b) \
    asm volatile("mma.sync.aligned.m16n8k16.row.col.f32.bf16.bf16.f32 " \
        "{%0,%1,%2,%3}, {%4,%5,%6,%7}, {%8,%9}, {%0,%1,%2,%3};" \
        : "+f"((d)[0]), "+f"((d)[1]), "+f"((d)[2]), "+f"((d)[3]) \
        : "r"((a)[0]), "r"((a)[1]), "r"((a)[2]), "r"((a)[3]), "r"((b)[0]), "r"((b)[1]))

__global__ void init_mm_kernel() {
    g_mm[0] = 0xFFFFFFFFu;
    g_mm[1] = 0u;
}

// ---------------- LayerNorm: one block per row, fp32 out -------------------
__global__ void layernorm_kernel(const float* __restrict__ x,
                                 const float* __restrict__ gamma,
                                 const float* __restrict__ beta) {
    int row = blockIdx.x, tid = threadIdx.x;
    const float4* xr = reinterpret_cast<const float4*>(x + (size_t)row * DIM);
    float4 xv = xr[tid];
    float s  = xv.x + xv.y + xv.z + xv.w;
    float ss = fmaf(xv.x, xv.x, fmaf(xv.y, xv.y, fmaf(xv.z, xv.z, xv.w * xv.w)));
    #pragma unroll
    for (int o = 16; o; o >>= 1) {
        s  += __shfl_xor_sync(0xffffffffu, s,  o);
        ss += __shfl_xor_sync(0xffffffffu, ss, o);
    }
    __shared__ float rs[8], rss[8];
    __shared__ float sm_mean, sm_inv;
    int w = tid >> 5, l = tid & 31;
    if (!l) { rs[w] = s; rss[w] = ss; }
    __syncthreads();
    if (tid == 0) {
        float S = 0.f, SS = 0.f;
        #pragma unroll
        for (int i = 0; i < 8; i++) { S += rs[i]; SS += rss[i]; }
        float mean = S * (1.f / DIM);
        float var  = SS * (1.f / DIM) - mean * mean;
        sm_mean = mean;
        sm_inv  = rsqrtf(var + 1e-5f);
    }
    __syncthreads();
    float mean = sm_mean, inv = sm_inv;
    float4 gv = reinterpret_cast<const float4*>(gamma)[tid];
    float4 bv = reinterpret_cast<const float4*>(beta)[tid];
    float4 o;
    o.x = (xv.x - mean) * inv * gv.x + bv.x;
    o.y = (xv.y - mean) * inv * gv.y + bv.y;
    o.z = (xv.z - mean) * inv * gv.z + bv.z;
    o.w = (xv.w - mean) * inv * gv.w + bv.w;
    reinterpret_cast<float4*>(g_xn)[(size_t)row * (DIM / 4) + tid] = o;
}

// ============ BIG GEMM (K=1024): R7-proven single-buffer, chunk 32 =========
// 128x128 CTA tile, 8 warps (2x4), warp tile 64x32, static 40KB smem,
// store;sync;prefetch;MMA;sync per chunk. ar[4]/br[4] prefetch (no spills).
// EPI 1: qkv   A=g_xn,   B=w_qkv -> scatter q(scaled)/k/v (fp32)
// EPI 2: out   A=exp((g_xsum-mn)*inv) fused in loader, B=w_out -> C + bias
#define RSTRIDE 80

template<int EPI>
__global__ __launch_bounds__(256)
void mma_gemm_big(const float* __restrict__ Bw, float* __restrict__ C,
                  const float* __restrict__ bias) {
    __shared__ __align__(16) char sAhi[128 * RSTRIDE];
    __shared__ __align__(16) char sAlo[128 * RSTRIDE];
    __shared__ __align__(16) char sBhi[128 * RSTRIDE];
    __shared__ __align__(16) char sBlo[128 * RSTRIDE];

    const float* A = (EPI == 1) ? g_xn : g_xsum;
    const float* B = Bw;

    float emn = 0.f, einv = 0.f;
    if (EPI == 2) {
        emn = fdec(g_mm[0]);
        float emx = fdec(g_mm[1]);
        einv = 1.0f / (emx - emn);
    }

    int tid = threadIdx.x;
    int bm = blockIdx.y * 128, bn = blockIdx.x * 128;

    // loader: thread t -> row t>>1, k-halfchunk (t&1)*16, 4x float4 each
    int lrow = tid >> 1, lcb = (tid & 1) * 16;
    const float* Ap = A + (size_t)(bm + lrow) * DIM + lcb;
    const float* Bp = B + (size_t)(bn + lrow) * DIM + lcb;

    float4 ar[4], br[4];
    #pragma unroll
    for (int i = 0; i < 4; i++) {
        ar[i] = *(const float4*)(Ap + i * 4);
        br[i] = *(const float4*)(Bp + i * 4);
    }

    int w = tid >> 5, l = tid & 31;
    int wm = w >> 2, wn = w & 3;           // 2 x 4 warp grid

    uint32_t aAhi = smem_u32(sAhi), aAlo = smem_u32(sAlo);
    uint32_t aBhi = smem_u32(sBhi), aBlo = smem_u32(sBlo);
    uint32_t aLane = (uint32_t)((l & 15) * RSTRIDE + (l >> 4) * 16);
    uint32_t bLane = (uint32_t)((l & 7) * RSTRIDE + ((l >> 3) & 1) * 16);
    uint32_t aWarp = (uint32_t)(wm * 64 * RSTRIDE);
    uint32_t bWarp = (uint32_t)(wn * 32 * RSTRIDE);

    float acc[4][4][4] = {};

    const int NS = DIM / 32;   // 32 chunks
    #pragma unroll 1
    for (int s = 0; s < NS; s++) {
        if (s) __syncthreads();            // previous compute done, smem reusable
        #pragma unroll
        for (int i = 0; i < 4; i++) {
            uint32_t off = (uint32_t)(lrow * RSTRIDE + (lcb + i * 4) * 2);
            float4 av = ar[i];
            if (EPI == 2) {                // fused exp((x-mn)*inv)
                av.x = expf((av.x - emn) * einv);
                av.y = expf((av.y - emn) * einv);
                av.z = expf((av.z - emn) * einv);
                av.w = expf((av.w - emn) * einv);
            }
            uint2 h, lo;
            f4_hilo(av, h, lo);
            *(uint2*)(sAhi + off) = h;  *(uint2*)(sAlo + off) = lo;
            f4_hilo(br[i], h, lo);
            *(uint2*)(sBhi + off) = h;  *(uint2*)(sBlo + off) = lo;
        }
        __syncthreads();
        if (s + 1 < NS) {                  // prefetch next chunk during HMMA
            #pragma unroll
            for (int i = 0; i < 4; i++) {
                ar[i] = *(const float4*)(Ap + (s + 1) * 32 + i * 4);
                br[i] = *(const float4*)(Bp + (s + 1) * 32 + i * 4);
            }
        }
        #pragma unroll
        for (int kk = 0; kk < 32; kk += 16) {
            uint32_t af[4][2][4];
            #pragma unroll
            for (int mi = 0; mi < 4; mi++) {
                uint32_t o = aWarp + (uint32_t)(mi * 16 * RSTRIDE + kk * 2) + aLane;
                LDSM_X4(af[mi][0], aAhi + o);
                LDSM_X4(af[mi][1], aAlo + o);
            }
            uint32_t bf[4][2][2];
            #pragma unroll
            for (int nj = 0; nj < 4; nj++) {
                uint32_t o = bWarp + (uint32_t)(nj * 8 * RSTRIDE + kk * 2) + bLane;
                LDSM_X2(bf[nj][0], aBhi + o);
                LDSM_X2(bf[nj][1], aBlo + o);
            }
            #pragma unroll
            for (int mi = 0; mi < 4; mi++)
                #pragma unroll
                for (int nj = 0; nj < 4; nj++) {
                    MMA16816(acc[mi][nj], af[mi][0], bf[nj][0]);   // hi*hi
                    MMA16816(acc[mi][nj], af[mi][0], bf[nj][1]);   // hi*lo
                    MMA16816(acc[mi][nj], af[mi][1], bf[nj][0]);   // lo*hi
                }
        }
    }

    // ---------------- epilogue from register accumulators ----------------
    #pragma unroll
    for (int mi = 0; mi < 4; mi++) {
        int row0 = bm + wm * 64 + mi * 16 + (l >> 2);
        #pragma unroll
        for (int nj = 0; nj < 4; nj++) {
            int col = bn + wn * 32 + nj * 8 + (l & 3) * 2;
            #pragma unroll
            for (int half = 0; half < 2; half++) {
                int m = row0 + half * 8;
                float v0 = acc[mi][nj][half * 2 + 0];
                float v1 = acc[mi][nj][half * 2 + 1];
                if (EPI == 1) {
                    int which = col >> 10;          // 0=q 1=k 2=v
                    int hh = (col & 1023) >> 6;
                    int dd = col & 63;
                    int bb = m >> 10, nn = m & 1023;
                    size_t o = (((size_t)(bb * NHEAD + hh)) * SEQ + nn) * HD + dd;
                    float sc = (which == 0) ? 0.125f : 1.0f;   // q pre-scale d^-0.5
                    float* dst = (which == 0 ? g_q : which == 1 ? g_k : g_v) + o;
                    *(float2*)dst = make_float2(v0 * sc, v1 * sc);
                } else {
                    float2* dst = (float2*)(C + (size_t)m * DIM + col);
                    *dst = make_float2(v0 + bias[col], v1 + bias[col + 1]);
                }
            }
        }
    }
}

// ============ SIM GEMM (K=64): R11-proven db mainloop, direct epilogue =====
// 128x128 CTA tile, K-chunk 32, double-buffered 2x40KB, one sync/chunk.
#define GSTAGE  40960
#define GSMEM   (2*GSTAGE)

__global__ __launch_bounds__(256, 2)
void mma_gemm_sim(int dummy) {
    extern __shared__ __align__(16) char dynsm[];

    size_t off0 = (size_t)blockIdx.z * SEQ * HD;
    const float* A = g_q + off0;
    const float* B = g_k + off0;

    int tid = threadIdx.x;
    int bm = blockIdx.y * 128, bn = blockIdx.x * 128;

    int lrow = tid >> 1, lcb = (tid & 1) * 16;
    const float* Ap = A + (size_t)(bm + lrow) * HD + lcb;
    const float* Bp = B + (size_t)(bn + lrow) * HD + lcb;

    float4 ar[4], br[4];
    #pragma unroll
    for (int i = 0; i < 4; i++) {
        ar[i] = *(const float4*)(Ap + i * 4);
        br[i] = *(const float4*)(Bp + i * 4);
    }
    {   // chunk 0 -> stage 0
        char* st = dynsm;
        #pragma unroll
        for (int i = 0; i < 4; i++) {
            uint32_t off = (uint32_t)(lrow * RSTRIDE + (lcb + i * 4) * 2);
            uint2 h, lo;
            f4_hilo(ar[i], h, lo);
            *(uint2*)(st + off) = h;            *(uint2*)(st + 10240 + off) = lo;
            f4_hilo(br[i], h, lo);
            *(uint2*)(st + 20480 + off) = h;    *(uint2*)(st + 30720 + off) = lo;
        }
    }

    int w = tid >> 5, l = tid & 31;
    int wm = w >> 2, wn = w & 3;
    uint32_t sb = smem_u32(dynsm);
    uint32_t aLane = (uint32_t)((l & 15) * RSTRIDE + (l >> 4) * 16);
    uint32_t bLane = (uint32_t)((l & 7) * RSTRIDE + ((l >> 3) & 1) * 16);
    uint32_t aWarp = (uint32_t)(wm * 64 * RSTRIDE);
    uint32_t bWarp = (uint32_t)(wn * 32 * RSTRIDE);

    float acc[4][4][4] = {};

    const int NS = HD / 32;   // 2 chunks
    #pragma unroll 1
    for (int s = 0; s < NS; s++) {
        __syncthreads();
        if (s + 1 < NS) {
            #pragma unroll
            for (int i = 0; i < 4; i++) {
                ar[i] = *(const float4*)(Ap + (s + 1) * 32 + i * 4);
                br[i] = *(const float4*)(Bp + (s + 1) * 32 + i * 4);
            }
        }
        uint32_t cur = sb + (uint32_t)(s & 1) * GSTAGE;
        uint32_t aAhi = cur, aAlo = cur + 10240, aBhi = cur + 20480, aBlo = cur + 30720;
        #pragma unroll
        for (int kk = 0; kk < 32; kk += 16) {
            uint32_t af[4][2][4];
            #pragma unroll
            for (int mi = 0; mi < 4; mi++) {
                uint32_t o = aWarp + (uint32_t)(mi * 16 * RSTRIDE + kk * 2) + aLane;
                LDSM_X4(af[mi][0], aAhi + o);
                LDSM_X4(af[mi][1], aAlo + o);
            }
            uint32_t bf[4][2][2];
            #pragma unroll
            for (int nj = 0; nj < 4; nj++) {
                uint32_t o = bWarp + (uint32_t)(nj * 8 * RSTRIDE + kk * 2) + bLane;
                LDSM_X2(bf[nj][0], aBhi + o);
                LDSM_X2(bf[nj][1], aBlo + o);
            }
            #pragma unroll
            for (int mi = 0; mi < 4; mi++)
                #pragma unroll
                for (int nj = 0; nj < 4; nj++) {
                    MMA16816(acc[mi][nj], af[mi][0], bf[nj][0]);
                    MMA16816(acc[mi][nj], af[mi][0], bf[nj][1]);
                    MMA16816(acc[mi][nj], af[mi][1], bf[nj][0]);
                }
        }
        if (s + 1 < NS) {
            char* st = dynsm + ((s + 1) & 1) * GSTAGE;
            #pragma unroll
            for (int i = 0; i < 4; i++) {
                uint32_t off = (uint32_t)(lrow * RSTRIDE + (lcb + i * 4) * 2);
                uint2 h, lo;
                f4_hilo(ar[i], h, lo);
                *(uint2*)(st + off) = h;            *(uint2*)(st + 10240 + off) = lo;
                f4_hilo(br[i], h, lo);
                *(uint2*)(st + 20480 + off) = h;    *(uint2*)(st + 30720 + off) = lo;
            }
        }
    }

    // direct epilogue (R11-proven)
    #pragma unroll
    for (int mi = 0; mi < 4; mi++) {
        int row0 = bm + wm * 64 + mi * 16 + (l >> 2);
        #pragma unroll
        for (int nj = 0; nj < 4; nj++) {
            int col = bn + wn * 32 + nj * 8 + (l & 3) * 2;
            #pragma unroll
            for (int half = 0; half < 2; half++) {
                int m = row0 + half * 8;
                float2* dst = (float2*)(g_sim + (size_t)blockIdx.z * SEQ * SEQ
                                        + (size_t)m * SEQ + col);
                *dst = make_float2(acc[mi][nj][half * 2 + 0],
                                   acc[mi][nj][half * 2 + 1]);
            }
        }
    }
}

// ------- top-32 select + gather-sum + fused global min/max -----------------
__global__ void topk_gather_kernel() {
    int warp = threadIdx.x >> 5;
    int lane = threadIdx.x & 31;
    int row  = blockIdx.x * 4 + warp;          // ((b*16+h)*1024 + nq)
    int bh   = row >> 10;

    const float* srow = g_sim + (size_t)row * SEQ;
    float vals[32];
    #pragma unroll
    for (int i = 0; i < 32; i++) vals[i] = srow[i * 32 + lane];   // j = i*32+lane

    float best = vals[0]; int bi = 0;
    #pragma unroll
    for (int i = 1; i < 32; i++)
        if (vals[i] > best) { best = vals[i]; bi = i; }

    int myidx = 0;
    #pragma unroll 1
    for (int r = 0; r < TOPK; r++) {
        unsigned e = fenc(best);
        unsigned wmax = __reduce_max_sync(0xffffffffu, e);
        unsigned msk = __ballot_sync(0xffffffffu, e == wmax);
        int wl = __ffs(msk) - 1;
        int wbi = __shfl_sync(0xffffffffu, bi, wl);
        int widx = wbi * 32 + wl;              // winning key index
        if (lane == r) myidx = widx;
        if (lane == wl) {                       // winner rescans its registers
            float nb = F_NINF; int nbi = 0;
            #pragma unroll
            for (int i = 0; i < 32; i++) {
                if (i == bi) vals[i] = F_NINF;
                if (vals[i] > nb) { nb = vals[i]; nbi = i; }
            }
            best = nb; bi = nbi;
        }
    }

    // unweighted gather-sum of the 32 selected V rows
    const float* vbase = g_v + (size_t)bh * SEQ * HD;
    float a0 = 0.f, a1 = 0.f;
    #pragma unroll 1
    for (int r = 0; r < TOPK; r++) {
        int idx = __shfl_sync(0xffffffffu, myidx, r);
        const float* vr = vbase + (size_t)idx * HD;
        a0 += vr[lane];
        a1 += vr[lane + 32];
    }

    int bb = row >> 14;
    int hh = (row >> 10) & 15;
    int nq = row & 1023;
    size_t o = ((size_t)(bb * SEQ + nq)) * DIM + hh * HD;   // [b,n,(h d)]
    g_xsum[o + lane]      = a0;
    g_xsum[o + lane + 32] = a1;

    // ---- fused global min/max: every g_xsum value is in exactly one warp --
    float mn = fminf(a0, a1), mx = fmaxf(a0, a1);
    #pragma unroll
    for (int off = 16; off; off >>= 1) {
        mn = fminf(mn, __shfl_xor_sync(0xffffffffu, mn, off));
        mx = fmaxf(mx, __shfl_xor_sync(0xffffffffu, mx, off));
    }
    __shared__ float smn[4], smx[4];
    if (!lane) { smn[warp] = mn; smx[warp] = mx; }
    __syncthreads();
    if (threadIdx.x == 0) {
        #pragma unroll
        for (int i = 1; i < 4; i++) { mn = fminf(mn, smn[i]); mx = fmaxf(mx, smx[i]); }
        atomicMin(&g_mm[0], fenc(mn));
        atomicMax(&g_mm[1], fenc(mx));
    }
}

// ---------------- launch ---------------------------------------------------
extern "C" void kernel_launch(void* const* d_in, const int* in_sizes, int n_in,
                              void* d_out, int out_size) {
    const float* x      = (const float*)d_in[0];
    const float* gamma  = (const float*)d_in[1];
    const float* beta   = (const float*)d_in[2];
    const float* w_qkv  = (const float*)d_in[3];
    const float* w_out  = (const float*)d_in[4];
    const float* b_out  = (const float*)d_in[5];
    float* out = (float*)d_out;

    cudaFuncSetAttribute((const void*)mma_gemm_sim,
                         cudaFuncAttributeMaxDynamicSharedMemorySize, GSMEM);

    init_mm_kernel<<<1, 1>>>();
    layernorm_kernel<<<NROWS, 256>>>(x, gamma, beta);
    // qkv: [4096,1024] @ [3072,1024]^T (HMMA bf16x3, R7 single-buffer)
    mma_gemm_big<1><<<dim3(24, 32, 1), 256>>>(w_qkv, nullptr, nullptr);
    // sim: 64 batched [1024,64] @ [1024,64]^T (R11 db kernel)
    mma_gemm_sim<<<dim3(8, 8, BH), 256, GSMEM>>>(0);
    // top-32 select + gather-sum + fused min/max
    topk_gather_kernel<<<BH * SEQ / 4, 128>>>();
    // out: exp-normalize fused into A-loader; [4096,1024] @ [1024,1024]^T + bias
    mma_gemm_big<2><<<dim3(8, 32, 1), 256>>>(w_out, out, b_out);
}

// round 15
// speedup vs baseline: 2.0609x; 1.0223x over previous
#include <cuda_runtime.h>
#include <cuda_bf16.h>
#include <cstdint>

#define DIM   1024
#define BATCH 4
#define SEQ   1024
#define NHEAD 16
#define HD    64
#define NROWS (BATCH*SEQ)     /* 4096 */
#define BH    (BATCH*NHEAD)   /* 64   */
#define TOPK  32

#define F_INF   __int_as_float(0x7f800000)
#define F_NINF  __int_as_float(0xff800000)

// ---------------- scratch (device globals; no allocation allowed) ----------
__device__ float g_xn[(size_t)NROWS*DIM];          // 16 MB  normalized x
__device__ float g_q[(size_t)BH*SEQ*HD];           // 16 MB  [b,h,n,d] (pre-scaled)
__device__ float g_k[(size_t)BH*SEQ*HD];           // 16 MB
__device__ float g_v[(size_t)BH*SEQ*HD];           // 16 MB
__device__ float g_sim[(size_t)BH*SEQ*SEQ];        // 256 MB [b,h,i,j]
__device__ float g_xsum[(size_t)NROWS*DIM];        // 16 MB  [b,n,(h d)] RAW sums
__device__ unsigned g_mm[2];                       // encoded min / max

// ---------------- helpers --------------------------------------------------
__device__ __forceinline__ uint32_t smem_u32(const void* p) {
    uint32_t a;
    asm("{ .reg .u64 t; cvta.to.shared.u64 t, %1; cvt.u32.u64 %0, t; }"
        : "=r"(a) : "l"(p));
    return a;
}

// fp32 float4 -> packed bf16 hi (uint2) and lo residual (uint2)
__device__ __forceinline__ void f4_hilo(float4 v, uint2& hi, uint2& lo) {
    __nv_bfloat16 h0 = __float2bfloat16(v.x), h1 = __float2bfloat16(v.y);
    __nv_bfloat16 h2 = __float2bfloat16(v.z), h3 = __float2bfloat16(v.w);
    __nv_bfloat16 l0 = __float2bfloat16(v.x - __bfloat162float(h0));
    __nv_bfloat16 l1 = __float2bfloat16(v.y - __bfloat162float(h1));
    __nv_bfloat16 l2 = __float2bfloat16(v.z - __bfloat162float(h2));
    __nv_bfloat16 l3 = __float2bfloat16(v.w - __bfloat162float(h3));
    hi.x = (uint32_t)__bfloat16_as_ushort(h0) | ((uint32_t)__bfloat16_as_ushort(h1) << 16);
    hi.y = (uint32_t)__bfloat16_as_ushort(h2) | ((uint32_t)__bfloat16_as_ushort(h3) << 16);
    lo.x = (uint32_t)__bfloat16_as_ushort(l0) | ((uint32_t)__bfloat16_as_ushort(l1) << 16);
    lo.y = (uint32_t)__bfloat16_as_ushort(l2) | ((uint32_t)__bfloat16_as_ushort(l3) << 16);
}

__device__ __forceinline__ unsigned fenc(float f) {
    unsigned u = __float_as_uint(f);
    return (u & 0x80000000u) ? ~u : (u | 0x80000000u);
}
__device__ __forceinline__ float fdec(unsigned u) {
    return __uint_as_float((u & 0x80000000u) ? (u ^ 0x80000000u) : ~u);
}

#define LDSM_X4(r, a) \
    asm volatile("ldmatrix.sync.aligned.m8n8.x4.shared.b16 {%0,%1,%2,%3}, [%4];" \
        : "=r"((r)[0]), "=r"((r)[1]), "=r"((r)[2]), "=r"((r)[3]) : "r"(a))
#define LDSM_X2(r, a) \
    asm volatile("ldmatrix.sync.aligned.m8n8.x2.shared.b16 {%0,%1}, [%2];" \
        : "=r"((r)[0]), "=r"((r)[1]) : "r"(a))
#define MMA16816(d, a, b) \
    asm volatile("mma.sync.aligned.m16n8k16.row.col.f32.bf16.bf16.f32 " \
        "{%0,%1,%2,%3}, {%4,%5,%6,%7}, {%8,%9}, {%0,%1,%2,%3};" \
        : "+f"((d)[0]), "+f"((d)[1]), "+f"((d)[2]), "+f"((d)[3]) \
        : "r"((a)[0]), "r"((a)[1]), "r"((a)[2]), "r"((a)[3]), "r"((b)[0]), "r"((b)[1]))

__global__ void init_mm_kernel() {
    g_mm[0] = 0xFFFFFFFFu;
    g_mm[1] = 0u;
}

// ---------------- LayerNorm: one block per row, fp32 out -------------------
__global__ void layernorm_kernel(const float* __restrict__ x,
                                 const float* __restrict__ gamma,
                                 const float* __restrict__ beta) {
    int row = blockIdx.x, tid = threadIdx.x;
    const float4* xr = reinterpret_cast<const float4*>(x + (size_t)row * DIM);
    float4 xv = xr[tid];
    float s  = xv.x + xv.y + xv.z + xv.w;
    float ss = fmaf(xv.x, xv.x, fmaf(xv.y, xv.y, fmaf(xv.z, xv.z, xv.w * xv.w)));
    #pragma unroll
    for (int o = 16; o; o >>= 1) {
        s  += __shfl_xor_sync(0xffffffffu, s,  o);
        ss += __shfl_xor_sync(0xffffffffu, ss, o);
    }
    __shared__ float rs[8], rss[8];
    __shared__ float sm_mean, sm_inv;
    int w = tid >> 5, l = tid & 31;
    if (!l) { rs[w] = s; rss[w] = ss; }
    __syncthreads();
    if (tid == 0) {
        float S = 0.f, SS = 0.f;
        #pragma unroll
        for (int i = 0; i < 8; i++) { S += rs[i]; SS += rss[i]; }
        float mean = S * (1.f / DIM);
        float var  = SS * (1.f / DIM) - mean * mean;
        sm_mean = mean;
        sm_inv  = rsqrtf(var + 1e-5f);
    }
    __syncthreads();
    float mean = sm_mean, inv = sm_inv;
    float4 gv = reinterpret_cast<const float4*>(gamma)[tid];
    float4 bv = reinterpret_cast<const float4*>(beta)[tid];
    float4 o;
    o.x = (xv.x - mean) * inv * gv.x + bv.x;
    o.y = (xv.y - mean) * inv * gv.y + bv.y;
    o.z = (xv.z - mean) * inv * gv.z + bv.z;
    o.w = (xv.w - mean) * inv * gv.w + bv.w;
    reinterpret_cast<float4*>(g_xn)[(size_t)row * (DIM / 4) + tid] = o;
}

// ============ BIG GEMM (K=1024): R11 db mainloop, NO reg cap ===============
// 128x128 CTA tile, K-chunk 32, 8 warps (2x4), warp tile 64x32.
// 2 dynamic smem stages of 40KB; one __syncthreads per chunk:
//   [sync; LDG s+1; MMA on stage s; cvt+STS s+1 into other stage]
// 1 CTA/SM (uncapped regs -> no spills).
// EPI 1: qkv   A=g_xn,   B=w_qkv -> scatter q(scaled)/k/v (fp32)
// EPI 2: out   A=exp((g_xsum-mn)*inv) fused in loader, B=w_out -> C + bias
#define RSTRIDE 80
#define GSTAGE  40960
#define GSMEM   (2*GSTAGE)

template<int EPI>
__global__ __launch_bounds__(256)
void mma_gemm_big(const float* __restrict__ Bw, float* __restrict__ C,
                  const float* __restrict__ bias) {
    extern __shared__ __align__(16) char dynsm[];

    const float* A = (EPI == 1) ? g_xn : g_xsum;
    const float* B = Bw;

    float emn = 0.f, einv = 0.f;
    if (EPI == 2) {
        emn = fdec(g_mm[0]);
        float emx = fdec(g_mm[1]);
        einv = 1.0f / (emx - emn);
    }

    int tid = threadIdx.x;
    int bm = blockIdx.y * 128, bn = blockIdx.x * 128;

    // loader: thread t -> row t>>1, k-halfchunk (t&1)*16, 4x float4 each
    int lrow = tid >> 1, lcb = (tid & 1) * 16;
    const float* Ap = A + (size_t)(bm + lrow) * DIM + lcb;
    const float* Bp = B + (size_t)(bn + lrow) * DIM + lcb;

    float4 ar[4], br[4];
    #pragma unroll
    for (int i = 0; i < 4; i++) {
        ar[i] = *(const float4*)(Ap + i * 4);
        br[i] = *(const float4*)(Bp + i * 4);
    }
    {   // chunk 0 -> cvt -> stage 0
        char* st = dynsm;
        #pragma unroll
        for (int i = 0; i < 4; i++) {
            uint32_t off = (uint32_t)(lrow * RSTRIDE + (lcb + i * 4) * 2);
            float4 av = ar[i];
            if (EPI == 2) {
                av.x = expf((av.x - emn) * einv);
                av.y = expf((av.y - emn) * einv);
                av.z = expf((av.z - emn) * einv);
                av.w = expf((av.w - emn) * einv);
            }
            uint2 h, lo;
            f4_hilo(av, h, lo);
            *(uint2*)(st + off) = h;            *(uint2*)(st + 10240 + off) = lo;
            f4_hilo(br[i], h, lo);
            *(uint2*)(st + 20480 + off) = h;    *(uint2*)(st + 30720 + off) = lo;
        }
    }

    int w = tid >> 5, l = tid & 31;
    int wm = w >> 2, wn = w & 3;           // 2 x 4 warp grid
    uint32_t sb = smem_u32(dynsm);
    uint32_t aLane = (uint32_t)((l & 15) * RSTRIDE + (l >> 4) * 16);
    uint32_t bLane = (uint32_t)((l & 7) * RSTRIDE + ((l >> 3) & 1) * 16);
    uint32_t aWarp = (uint32_t)(wm * 64 * RSTRIDE);
    uint32_t bWarp = (uint32_t)(wn * 32 * RSTRIDE);

    float acc[4][4][4] = {};

    const int NS = DIM / 32;   // 32 chunks
    #pragma unroll 1
    for (int s = 0; s < NS; s++) {
        __syncthreads();       // stage s&1 filled and visible; other stage free
        if (s + 1 < NS) {      // LDG next chunk (overlaps MMA below)
            #pragma unroll
            for (int i = 0; i < 4; i++) {
                ar[i] = *(const float4*)(Ap + (s + 1) * 32 + i * 4);
                br[i] = *(const float4*)(Bp + (s + 1) * 32 + i * 4);
            }
        }
        uint32_t cur = sb + (uint32_t)(s & 1) * GSTAGE;
        uint32_t aAhi = cur, aAlo = cur + 10240, aBhi = cur + 20480, aBlo = cur + 30720;
        #pragma unroll
        for (int kk = 0; kk < 32; kk += 16) {
            uint32_t af[4][2][4];
            #pragma unroll
            for (int mi = 0; mi < 4; mi++) {
                uint32_t o = aWarp + (uint32_t)(mi * 16 * RSTRIDE + kk * 2) + aLane;
                LDSM_X4(af[mi][0], aAhi + o);
                LDSM_X4(af[mi][1], aAlo + o);
            }
            uint32_t bf[4][2][2];
            #pragma unroll
            for (int nj = 0; nj < 4; nj++) {
                uint32_t o = bWarp + (uint32_t)(nj * 8 * RSTRIDE + kk * 2) + bLane;
                LDSM_X2(bf[nj][0], aBhi + o);
                LDSM_X2(bf[nj][1], aBlo + o);
            }
            #pragma unroll
            for (int mi = 0; mi < 4; mi++)
                #pragma unroll
                for (int nj = 0; nj < 4; nj++) {
                    MMA16816(acc[mi][nj], af[mi][0], bf[nj][0]);   // hi*hi
                    MMA16816(acc[mi][nj], af[mi][0], bf[nj][1]);   // hi*lo
                    MMA16816(acc[mi][nj], af[mi][1], bf[nj][0]);   // lo*hi
                }
        }
        if (s + 1 < NS) {      // cvt + STS into the other stage
            char* st = dynsm + ((s + 1) & 1) * GSTAGE;
            #pragma unroll
            for (int i = 0; i < 4; i++) {
                uint32_t off = (uint32_t)(lrow * RSTRIDE + (lcb + i * 4) * 2);
                float4 av = ar[i];
                if (EPI == 2) {
                    av.x = expf((av.x - emn) * einv);
                    av.y = expf((av.y - emn) * einv);
                    av.z = expf((av.z - emn) * einv);
                    av.w = expf((av.w - emn) * einv);
                }
                uint2 h, lo;
                f4_hilo(av, h, lo);
                *(uint2*)(st + off) = h;            *(uint2*)(st + 10240 + off) = lo;
                f4_hilo(br[i], h, lo);
                *(uint2*)(st + 20480 + off) = h;    *(uint2*)(st + 30720 + off) = lo;
            }
        }
    }

    // ---------------- epilogue from register accumulators ----------------
    #pragma unroll
    for (int mi = 0; mi < 4; mi++) {
        int row0 = bm + wm * 64 + mi * 16 + (l >> 2);
        #pragma unroll
        for (int nj = 0; nj < 4; nj++) {
            int col = bn + wn * 32 + nj * 8 + (l & 3) * 2;
            #pragma unroll
            for (int half = 0; half < 2; half++) {
                int m = row0 + half * 8;
                float v0 = acc[mi][nj][half * 2 + 0];
                float v1 = acc[mi][nj][half * 2 + 1];
                if (EPI == 1) {
                    int which = col >> 10;          // 0=q 1=k 2=v
                    int hh = (col & 1023) >> 6;
                    int dd = col & 63;
                    int bb = m >> 10, nn = m & 1023;
                    size_t o = (((size_t)(bb * NHEAD + hh)) * SEQ + nn) * HD + dd;
                    float sc = (which == 0) ? 0.125f : 1.0f;   // q pre-scale d^-0.5
                    float* dst = (which == 0 ? g_q : which == 1 ? g_k : g_v) + o;
                    *(float2*)dst = make_float2(v0 * sc, v1 * sc);
                } else {
                    float2* dst = (float2*)(C + (size_t)m * DIM + col);
                    *dst = make_float2(v0 + bias[col], v1 + bias[col + 1]);
                }
            }
        }
    }
}

// ============ SIM GEMM (K=64): R11-proven db mainloop, direct epilogue =====
__global__ __launch_bounds__(256, 2)
void mma_gemm_sim(int dummy) {
    extern __shared__ __align__(16) char dynsm[];

    size_t off0 = (size_t)blockIdx.z * SEQ * HD;
    const float* A = g_q + off0;
    const float* B = g_k + off0;

    int tid = threadIdx.x;
    int bm = blockIdx.y * 128, bn = blockIdx.x * 128;

    int lrow = tid >> 1, lcb = (tid & 1) * 16;
    const float* Ap = A + (size_t)(bm + lrow) * HD + lcb;
    const float* Bp = B + (size_t)(bn + lrow) * HD + lcb;

    float4 ar[4], br[4];
    #pragma unroll
    for (int i = 0; i < 4; i++) {
        ar[i] = *(const float4*)(Ap + i * 4);
        br[i] = *(const float4*)(Bp + i * 4);
    }
    {   // chunk 0 -> stage 0
        char* st = dynsm;
        #pragma unroll
        for (int i = 0; i < 4; i++) {
            uint32_t off = (uint32_t)(lrow * RSTRIDE + (lcb + i * 4) * 2);
            uint2 h, lo;
            f4_hilo(ar[i], h, lo);
            *(uint2*)(st + off) = h;            *(uint2*)(st + 10240 + off) = lo;
            f4_hilo(br[i], h, lo);
            *(uint2*)(st + 20480 + off) = h;    *(uint2*)(st + 30720 + off) = lo;
        }
    }

    int w = tid >> 5, l = tid & 31;
    int wm = w >> 2, wn = w & 3;
    uint32_t sb = smem_u32(dynsm);
    uint32_t aLane = (uint32_t)((l & 15) * RSTRIDE + (l >> 4) * 16);
    uint32_t bLane = (uint32_t)((l & 7) * RSTRIDE + ((l >> 3) & 1) * 16);
    uint32_t aWarp = (uint32_t)(wm * 64 * RSTRIDE);
    uint32_t bWarp = (uint32_t)(wn * 32 * RSTRIDE);

    float acc[4][4][4] = {};

    const int NS = HD / 32;   // 2 chunks
    #pragma unroll 1
    for (int s = 0; s < NS; s++) {
        __syncthreads();
        if (s + 1 < NS) {
            #pragma unroll
            for (int i = 0; i < 4; i++) {
                ar[i] = *(const float4*)(Ap + (s + 1) * 32 + i * 4);
                br[i] = *(const float4*)(Bp + (s + 1) * 32 + i * 4);
            }
        }
        uint32_t cur = sb + (uint32_t)(s & 1) * GSTAGE;
        uint32_t aAhi = cur, aAlo = cur + 10240, aBhi = cur + 20480, aBlo = cur + 30720;
        #pragma unroll
        for (int kk = 0; kk < 32; kk += 16) {
            uint32_t af[4][2][4];
            #pragma unroll
            for (int mi = 0; mi < 4; mi++) {
                uint32_t o = aWarp + (uint32_t)(mi * 16 * RSTRIDE + kk * 2) + aLane;
                LDSM_X4(af[mi][0], aAhi + o);
                LDSM_X4(af[mi][1], aAlo + o);
            }
            uint32_t bf[4][2][2];
            #pragma unroll
            for (int nj = 0; nj < 4; nj++) {
                uint32_t o = bWarp + (uint32_t)(nj * 8 * RSTRIDE + kk * 2) + bLane;
                LDSM_X2(bf[nj][0], aBhi + o);
                LDSM_X2(bf[nj][1], aBlo + o);
            }
            #pragma unroll
            for (int mi = 0; mi < 4; mi++)
                #pragma unroll
                for (int nj = 0; nj < 4; nj++) {
                    MMA16816(acc[mi][nj], af[mi][0], bf[nj][0]);
                    MMA16816(acc[mi][nj], af[mi][0], bf[nj][1]);
                    MMA16816(acc[mi][nj], af[mi][1], bf[nj][0]);
                }
        }
        if (s + 1 < NS) {
            char* st = dynsm + ((s + 1) & 1) * GSTAGE;
            #pragma unroll
            for (int i = 0; i < 4; i++) {
                uint32_t off = (uint32_t)(lrow * RSTRIDE + (lcb + i * 4) * 2);
                uint2 h, lo;
                f4_hilo(ar[i], h, lo);
                *(uint2*)(st + off) = h;            *(uint2*)(st + 10240 + off) = lo;
                f4_hilo(br[i], h, lo);
                *(uint2*)(st + 20480 + off) = h;    *(uint2*)(st + 30720 + off) = lo;
            }
        }
    }

    // direct epilogue (R11-proven)
    #pragma unroll
    for (int mi = 0; mi < 4; mi++) {
        int row0 = bm + wm * 64 + mi * 16 + (l >> 2);
        #pragma unroll
        for (int nj = 0; nj < 4; nj++) {
            int col = bn + wn * 32 + nj * 8 + (l & 3) * 2;
            #pragma unroll
            for (int half = 0; half < 2; half++) {
                int m = row0 + half * 8;
                float2* dst = (float2*)(g_sim + (size_t)blockIdx.z * SEQ * SEQ
                                        + (size_t)m * SEQ + col);
                *dst = make_float2(acc[mi][nj][half * 2 + 0],
                                   acc[mi][nj][half * 2 + 1]);
            }
        }
    }
}

// ------- top-32 select + gather-sum + fused global min/max -----------------
__global__ void topk_gather_kernel() {
    int warp = threadIdx.x >> 5;
    int lane = threadIdx.x & 31;
    int row  = blockIdx.x * 4 + warp;          // ((b*16+h)*1024 + nq)
    int bh   = row >> 10;

    const float* srow = g_sim + (size_t)row * SEQ;
    float vals[32];
    #pragma unroll
    for (int i = 0; i < 32; i++) vals[i] = srow[i * 32 + lane];   // j = i*32+lane

    float best = vals[0]; int bi = 0;
    #pragma unroll
    for (int i = 1; i < 32; i++)
        if (vals[i] > best) { best = vals[i]; bi = i; }

    int myidx = 0;
    #pragma unroll 1
    for (int r = 0; r < TOPK; r++) {
        unsigned e = fenc(best);
        unsigned wmax = __reduce_max_sync(0xffffffffu, e);
        unsigned msk = __ballot_sync(0xffffffffu, e == wmax);
        int wl = __ffs(msk) - 1;
        int wbi = __shfl_sync(0xffffffffu, bi, wl);
        int widx = wbi * 32 + wl;              // winning key index
        if (lane == r) myidx = widx;
        if (lane == wl) {                       // winner rescans its registers
            float nb = F_NINF; int nbi = 0;
            #pragma unroll
            for (int i = 0; i < 32; i++) {
                if (i == bi) vals[i] = F_NINF;
                if (vals[i] > nb) { nb = vals[i]; nbi = i; }
            }
            best = nb; bi = nbi;
        }
    }

    // unweighted gather-sum of the 32 selected V rows (unroll 4 -> MLP)
    const float* vbase = g_v + (size_t)bh * SEQ * HD;
    float a0 = 0.f, a1 = 0.f;
    #pragma unroll 4
    for (int r = 0; r < TOPK; r++) {
        int idx = __shfl_sync(0xffffffffu, myidx, r);
        const float* vr = vbase + (size_t)idx * HD;
        a0 += vr[lane];
        a1 += vr[lane + 32];
    }

    int bb = row >> 14;
    int hh = (row >> 10) & 15;
    int nq = row & 1023;
    size_t o = ((size_t)(bb * SEQ + nq)) * DIM + hh * HD;   // [b,n,(h d)]
    g_xsum[o + lane]      = a0;
    g_xsum[o + lane + 32] = a1;

    // ---- fused global min/max: every g_xsum value is in exactly one warp --
    float mn = fminf(a0, a1), mx = fmaxf(a0, a1);
    #pragma unroll
    for (int off = 16; off; off >>= 1) {
        mn = fminf(mn, __shfl_xor_sync(0xffffffffu, mn, off));
        mx = fmaxf(mx, __shfl_xor_sync(0xffffffffu, mx, off));
    }
    __shared__ float smn[4], smx[4];
    if (!lane) { smn[warp] = mn; smx[warp] = mx; }
    __syncthreads();
    if (threadIdx.x == 0) {
        #pragma unroll
        for (int i = 1; i < 4; i++) { mn = fminf(mn, smn[i]); mx = fmaxf(mx, smx[i]); }
        atomicMin(&g_mm[0], fenc(mn));
        atomicMax(&g_mm[1], fenc(mx));
    }
}

// ---------------- launch ---------------------------------------------------
extern "C" void kernel_launch(void* const* d_in, const int* in_sizes, int n_in,
                              void* d_out, int out_size) {
    const float* x      = (const float*)d_in[0];
    const float* gamma  = (const float*)d_in[1];
    const float* beta   = (const float*)d_in[2];
    const float* w_qkv  = (const float*)d_in[3];
    const float* w_out  = (const float*)d_in[4];
    const float* b_out  = (const float*)d_in[5];
    float* out = (float*)d_out;

    cudaFuncSetAttribute((const void*)mma_gemm_big<1>,
                         cudaFuncAttributeMaxDynamicSharedMemorySize, GSMEM);
    cudaFuncSetAttribute((const void*)mma_gemm_big<2>,
                         cudaFuncAttributeMaxDynamicSharedMemorySize, GSMEM);
    cudaFuncSetAttribute((const void*)mma_gemm_sim,
                         cudaFuncAttributeMaxDynamicSharedMemorySize, GSMEM);

    init_mm_kernel<<<1, 1>>>();
    layernorm_kernel<<<NROWS, 256>>>(x, gamma, beta);
    // qkv: [4096,1024] @ [3072,1024]^T (HMMA bf16x3, db uncapped)
    mma_gemm_big<1><<<dim3(24, 32, 1), 256, GSMEM>>>(w_qkv, nullptr, nullptr);
    // sim: 64 batched [1024,64] @ [1024,64]^T (R11 db kernel)
    mma_gemm_sim<<<dim3(8, 8, BH), 256, GSMEM>>>(0);
    // top-32 select + gather-sum + fused min/max
    topk_gather_kernel<<<BH * SEQ / 4, 128>>>();
    // out: exp-normalize fused into A-loader; [4096,1024] @ [1024,1024]^T + bias
    mma_gemm_big<2><<<dim3(8, 32, 1), 256, GSMEM>>>(w_out, out, b_out);
}